// round 7
// baseline (speedup 1.0000x reference)
#include <cuda_runtime.h>
#include <cuda_bf16.h>
#include <math.h>
#include <stdint.h>

#define EMBED  1024
#define HEADS  16
#define HD     64
#define BATCH  2
#define SEQ    2048
#define MROWS  (BATCH*SEQ)   // 4096
#define KSPLIT 3072          // 3*EMBED augmented K
#define SC2F   0.1803368801111601f   // (1/sqrt(64)) * log2(e)

// ---------------- scratch (device globals; no allocation) ----------------
__device__ __nv_bfloat16 g_Xs[MROWS*KSPLIT];       // split activations [hi|lo|hi]
__device__ __nv_bfloat16 g_Ws[4*EMBED*KSPLIT];     // split weights     [hi|hi|lo]
__device__ __nv_bfloat16 g_Qh[BATCH*HEADS*SEQ*HD]; // bf16 hi/lo, [bh][s][d]
__device__ __nv_bfloat16 g_Ql[BATCH*HEADS*SEQ*HD];
__device__ __nv_bfloat16 g_Kh[BATCH*HEADS*SEQ*HD];
__device__ __nv_bfloat16 g_Kl[BATCH*HEADS*SEQ*HD];
__device__ __nv_bfloat16 g_Vh[BATCH*HEADS*SEQ*HD];
__device__ __nv_bfloat16 g_Vl[BATCH*HEADS*SEQ*HD];

// ============================ helpers ================================
__device__ __forceinline__ uint32_t smem_u32(const void* p) {
    uint32_t a;
    asm("{ .reg .u64 t; cvta.to.shared.u64 t, %1; cvt.u32.u64 %0, t; }"
        : "=r"(a) : "l"(p));
    return a;
}
__device__ __forceinline__ void cp_async16(uint32_t dst, const void* src) {
    asm volatile("cp.async.cg.shared.global [%0], [%1], 16;"
                 :: "r"(dst), "l"(src) : "memory");
}
__device__ __forceinline__ void cp_commit() {
    asm volatile("cp.async.commit_group;" ::: "memory");
}
__device__ __forceinline__ void cp_wait0() {
    asm volatile("cp.async.wait_group 0;" ::: "memory");
}
__device__ __forceinline__ void cp_wait1() {
    asm volatile("cp.async.wait_group 1;" ::: "memory");
}
__device__ __forceinline__ void ldsm_x4(uint32_t& r0, uint32_t& r1,
                                        uint32_t& r2, uint32_t& r3, uint32_t addr) {
    asm volatile("ldmatrix.sync.aligned.m8n8.x4.shared.b16 {%0,%1,%2,%3}, [%4];"
                 : "=r"(r0), "=r"(r1), "=r"(r2), "=r"(r3) : "r"(addr));
}
__device__ __forceinline__ void ldsm_x4t(uint32_t& r0, uint32_t& r1,
                                         uint32_t& r2, uint32_t& r3, uint32_t addr) {
    asm volatile("ldmatrix.sync.aligned.m8n8.x4.trans.shared.b16 {%0,%1,%2,%3}, [%4];"
                 : "=r"(r0), "=r"(r1), "=r"(r2), "=r"(r3) : "r"(addr));
}
__device__ __forceinline__ void mma16816(float* c, const uint32_t* a,
                                         uint32_t b0, uint32_t b1) {
    asm volatile(
        "mma.sync.aligned.m16n8k16.row.col.f32.bf16.bf16.f32 "
        "{%0,%1,%2,%3}, {%4,%5,%6,%7}, {%8,%9}, {%0,%1,%2,%3};"
        : "+f"(c[0]), "+f"(c[1]), "+f"(c[2]), "+f"(c[3])
        : "r"(a[0]), "r"(a[1]), "r"(a[2]), "r"(a[3]), "r"(b0), "r"(b1));
}
// pack: lo half = a, hi half = b
__device__ __forceinline__ uint32_t bf16x2(float a, float b) {
    uint32_t r;
    asm("cvt.rn.bf16x2.f32 %0, %1, %2;" : "=r"(r) : "f"(b), "f"(a));
    return r;
}
// fma-pipe exp2 (poly-4, rel err ~4e-5), input clamped to [-80, 0]
__device__ __forceinline__ float exp2_poly(float d) {
    d = fmaxf(d, -80.f);
    float t = d + 12582912.f;
    int ib = __float_as_int(t);
    float f = d - (t - 12582912.f);
    float p = 0.009618130f;
    p = fmaf(p, f, 0.055504110f);
    p = fmaf(p, f, 0.240226507f);
    p = fmaf(p, f, 0.693147181f);
    p = fmaf(p, f, 1.0f);
    return __int_as_float(__float_as_int(p) + (ib << 23));
}

// ============================ split kernels ==============================
__global__ void split_act(const float* __restrict__ in, __nv_bfloat16* __restrict__ out) {
    int idx = blockIdx.x * 256 + threadIdx.x;
    int r = idx >> 10, c = idx & 1023;
    float v = in[idx];
    __nv_bfloat16 hi = __float2bfloat16(v);
    __nv_bfloat16 lo = __float2bfloat16(v - __bfloat162float(hi));
    size_t o = (size_t)r * KSPLIT + c;
    out[o] = hi; out[o + 1024] = lo; out[o + 2048] = hi;
}
__global__ void split_wgt(const float* __restrict__ in, __nv_bfloat16* __restrict__ out) {
    int idx = blockIdx.x * 256 + threadIdx.x;
    int r = idx >> 10, c = idx & 1023;
    float v = in[idx];
    __nv_bfloat16 hi = __float2bfloat16(v);
    __nv_bfloat16 lo = __float2bfloat16(v - __bfloat162float(hi));
    size_t o = (size_t)r * KSPLIT + c;
    out[o] = hi; out[o + 1024] = hi; out[o + 2048] = lo;
}

// ============================ HMMA GEMM ===============================
// C[4096,1024] = A'[4096,3072] * W'[1024,3072]^T  (bf16 in, fp32 accum)
// grid (8, 32, nz); mode = mode_base + blockIdx.z selects W slice + dest.
#define KTILE   64
#define NSTEP   (KSPLIT/KTILE)          // 48
#define TILE_AB (128*144)
#define BUFSZ   (2*TILE_AB)
#define GEMM_SMEM (2*BUFSZ)             // 73728

__device__ __forceinline__ void load_tile(uint32_t smb, int buf,
                                          const __nv_bfloat16* __restrict__ A,
                                          const __nv_bfloat16* __restrict__ W,
                                          int m0, int n0, int kbase, int tid) {
    uint32_t base = smb + buf * BUFSZ;
#pragma unroll
    for (int i = 0; i < 4; i++) {
        int c = tid + i * 256;
        int row = c >> 3, kc = (c & 7) * 8;
        cp_async16(base + row * 144 + kc * 2,
                   A + (size_t)(m0 + row) * KSPLIT + kbase + kc);
    }
#pragma unroll
    for (int i = 0; i < 4; i++) {
        int c = tid + i * 256;
        int row = c >> 3, kc = (c & 7) * 8;
        cp_async16(base + TILE_AB + row * 144 + kc * 2,
                   W + (size_t)(n0 + row) * KSPLIT + kbase + kc);
    }
}

__global__ __launch_bounds__(256, 2) void gemm_mma(const __nv_bfloat16* __restrict__ A,
                                                   const __nv_bfloat16* __restrict__ Wbase,
                                                   float* __restrict__ Cext, int mode_base)
{
    extern __shared__ char sm[];
    uint32_t smb = smem_u32(sm);
    int tid = threadIdx.x;
    int warp = tid >> 5, lane = tid & 31;
    int wm = warp & 1, wn = warp >> 1;
    int m0 = blockIdx.y * 128;
    int n0 = blockIdx.x * 128;
    int mode = mode_base + blockIdx.z;
    const __nv_bfloat16* W = Wbase + (size_t)blockIdx.z * EMBED * KSPLIT;

    float acc[4][4][4];
#pragma unroll
    for (int i = 0; i < 4; i++)
#pragma unroll
        for (int j = 0; j < 4; j++)
#pragma unroll
            for (int q = 0; q < 4; q++) acc[i][j][q] = 0.f;

    load_tile(smb, 0, A, W, m0, n0, 0, tid);
    cp_commit();
    cp_wait0();
    __syncthreads();

    uint32_t aoff = (uint32_t)((wm * 64 + (lane & 15)) * 144 + (lane >> 4) * 16);
    uint32_t boff = (uint32_t)(TILE_AB + (wn * 32 + (lane & 15)) * 144 + (lane >> 4) * 16);

    for (int kt = 0; kt < NSTEP; kt++) {
        int b = kt & 1;
        if (kt + 1 < NSTEP) {
            load_tile(smb, b ^ 1, A, W, m0, n0, (kt + 1) * KTILE, tid);
            cp_commit();
        }
        uint32_t abase = smb + b * BUFSZ + aoff;
        uint32_t bbase = smb + b * BUFSZ + boff;
#pragma unroll
        for (int kk = 0; kk < 4; kk++) {
            uint32_t af[4][4];
#pragma unroll
            for (int mf = 0; mf < 4; mf++)
                ldsm_x4(af[mf][0], af[mf][1], af[mf][2], af[mf][3],
                        abase + mf * 16 * 144 + kk * 32);
#pragma unroll
            for (int nb = 0; nb < 2; nb++) {
                uint32_t b0, b1, b2, b3;
                ldsm_x4(b0, b1, b2, b3, bbase + nb * 16 * 144 + kk * 32);
#pragma unroll
                for (int mf = 0; mf < 4; mf++) {
                    mma16816(acc[mf][nb * 2 + 0], af[mf], b0, b2);
                    mma16816(acc[mf][nb * 2 + 1], af[mf], b1, b3);
                }
            }
        }
        if (kt + 1 < NSTEP) cp_wait0();
        __syncthreads();
    }

    int lr = lane >> 2, lc = (lane & 3) * 2;
#pragma unroll
    for (int mf = 0; mf < 4; mf++) {
#pragma unroll
        for (int nf = 0; nf < 4; nf++) {
            int col = n0 + wn * 32 + nf * 8 + lc;
#pragma unroll
            for (int half = 0; half < 2; half++) {
                int row = m0 + wm * 64 + mf * 16 + lr + half * 8;
                float vx = acc[mf][nf][half * 2 + 0];
                float vy = acc[mf][nf][half * 2 + 1];
                if (mode == 3) {
                    *(float2*)(Cext + (size_t)row * EMBED + col) = make_float2(vx, vy);
                } else {
                    if (mode == 0) { vx *= SC2F; vy *= SC2F; }
                    uint32_t hp = bf16x2(vx, vy);
                    float h0 = __int_as_float(hp << 16);
                    float h1 = __int_as_float(hp & 0xFFFF0000u);
                    uint32_t lp = bf16x2(vx - h0, vy - h1);
                    int bb = row >> 11, s = row & 2047;
                    int h = col >> 6, d = col & 63;
                    size_t idx = (((size_t)(bb * HEADS + h) * SEQ + s) * HD + d);
                    __nv_bfloat16 *dh, *dl;
                    if (mode == 0)      { dh = g_Qh; dl = g_Ql; }
                    else if (mode == 1) { dh = g_Kh; dl = g_Kl; }
                    else                { dh = g_Vh; dl = g_Vl; }
                    *(uint32_t*)(dh + idx) = hp;
                    *(uint32_t*)(dl + idx) = lp;
                }
            }
        }
    }
}

// =========================================================================
// Flash attention: HMMA split-bf16, log2-domain softmax, hybrid exp.
// 2 CTAs/SM (smem 106KB x2 = 213KB < 228KB carveout).
// =========================================================================
#define QSTR  272               // Q2/K2 row stride bytes (136 bf16)
#define VSTR  144               // V2 row stride bytes (72 bf16)
#define Q2SZ  (128*QSTR)        // 34816
#define K2SZ  (64*QSTR)         // 17408
#define V2SZ  (128*VSTR)        // 18432
#define KVSZ  (K2SZ+V2SZ)
#define FLASH_SMEM (Q2SZ + 2*KVSZ)   // 106496

__device__ __forceinline__ void flash_load_kv(uint32_t smb, int buf, int k0,
                                              const __nv_bfloat16* Kh, const __nv_bfloat16* Kl,
                                              const __nv_bfloat16* Vh, const __nv_bfloat16* Vl,
                                              int tid) {
    uint32_t kb = smb + Q2SZ + buf * KVSZ;
    uint32_t vb = kb + K2SZ;
#pragma unroll
    for (int i = 0; i < 4; i++) {
        int id = tid + i * 256;
        int row = id >> 4, half = (id >> 3) & 1, c8 = id & 7;
        cp_async16(kb + row * QSTR + half * 128 + c8 * 16,
                   (half ? Kl : Kh) + (size_t)(k0 + row) * HD + c8 * 8);
    }
#pragma unroll
    for (int i = 0; i < 4; i++) {
        int id = tid + i * 256;
        int row = id >> 3, c8 = id & 7;
        cp_async16(vb + row * VSTR + c8 * 16,
                   (row < 64 ? Vh : Vl) + (size_t)(k0 + (row & 63)) * HD + c8 * 8);
    }
}

__global__ __launch_bounds__(256, 2) void flash2()
{
    extern __shared__ char sm[];
    uint32_t smb = smem_u32(sm);
    int tid = threadIdx.x;
    int warp = tid >> 5, lane = tid & 31;
    int bh = blockIdx.y;
    int qt = (int)gridDim.x - 1 - blockIdx.x;   // heavy tiles first
    int q0 = qt * 128;

    size_t base = (size_t)bh * SEQ * HD;
    const __nv_bfloat16 *Qh = g_Qh + base, *Ql = g_Ql + base;
    const __nv_bfloat16 *Kh = g_Kh + base, *Kl = g_Kl + base;
    const __nv_bfloat16 *Vh = g_Vh + base, *Vl = g_Vl + base;

#pragma unroll
    for (int i = 0; i < 8; i++) {
        int id = tid + i * 256;
        int row = id >> 4, half = (id >> 3) & 1, c8 = id & 7;
        cp_async16(smb + row * QSTR + half * 128 + c8 * 16,
                   (half ? Ql : Qh) + (size_t)(q0 + row) * HD + c8 * 8);
    }
    flash_load_kv(smb, 0, 0, Kh, Kl, Vh, Vl, tid);
    cp_commit();

    float O[8][4];
#pragma unroll
    for (int f = 0; f < 8; f++)
#pragma unroll
        for (int q = 0; q < 4; q++) O[f][q] = 0.f;
    float m0v = -1e30f, m1v = -1e30f, l0 = 0.f, l1 = 0.f;

    uint32_t aoff = (uint32_t)((warp * 16 + (lane & 15)) * QSTR + (lane >> 4) * 16);
    uint32_t koff = (uint32_t)((lane & 15) * QSTR + (lane >> 4) * 16);
    uint32_t voff = (uint32_t)((lane & 15) * VSTR + (lane >> 4) * 16);

    int nkt = 2 * (qt + 1);
    int rg0 = q0 + warp * 16 + (lane >> 2);
    int cg0 = 2 * (lane & 3);

    for (int kt = 0; kt < nkt; kt++) {
        int buf = kt & 1;
        int k0 = kt * 64;
        if (kt + 1 < nkt) {
            flash_load_kv(smb, buf ^ 1, (kt + 1) * 64, Kh, Kl, Vh, Vl, tid);
            cp_commit();
            cp_wait1();
        } else {
            cp_wait0();
        }
        __syncthreads();

        // ---- S = Q' K'^T ----
        float S[8][4];
#pragma unroll
        for (int f = 0; f < 8; f++)
#pragma unroll
            for (int q = 0; q < 4; q++) S[f][q] = 0.f;
        uint32_t kbuf = smb + Q2SZ + buf * KVSZ;
#pragma unroll
        for (int c = 0; c < 12; c++) {
            int ac = (c < 8) ? c : c - 8;
            int bc = (c < 8) ? (c & 3) : 4 + (c & 3);
            uint32_t a[4];
            ldsm_x4(a[0], a[1], a[2], a[3], smb + aoff + ac * 32);
#pragma unroll
            for (int g = 0; g < 4; g++) {
                uint32_t b0, b1, b2, b3;
                ldsm_x4(b0, b1, b2, b3, kbuf + koff + g * 16 * QSTR + bc * 32);
                mma16816(S[2 * g + 0], a, b0, b2);
                mma16816(S[2 * g + 1], a, b1, b3);
            }
        }

        // ---- causal mask ----
        if (kt >= nkt - 2) {
#pragma unroll
            for (int f = 0; f < 8; f++) {
                int key = k0 + 8 * f + cg0;
#pragma unroll
                for (int q = 0; q < 4; q++) {
                    int kcol = key + (q & 1);
                    int row = rg0 + (q >> 1) * 8;
                    if (kcol > row) S[f][q] = -1e30f;
                }
            }
        }

        // ---- online softmax (log2 domain) ----
        float mx0 = -1e30f, mx1 = -1e30f;
#pragma unroll
        for (int f = 0; f < 8; f++) {
            mx0 = fmaxf(mx0, fmaxf(S[f][0], S[f][1]));
            mx1 = fmaxf(mx1, fmaxf(S[f][2], S[f][3]));
        }
        mx0 = fmaxf(mx0, __shfl_xor_sync(0xffffffffu, mx0, 1));
        mx0 = fmaxf(mx0, __shfl_xor_sync(0xffffffffu, mx0, 2));
        mx1 = fmaxf(mx1, __shfl_xor_sync(0xffffffffu, mx1, 1));
        mx1 = fmaxf(mx1, __shfl_xor_sync(0xffffffffu, mx1, 2));
        float mn0 = fmaxf(m0v, mx0), mn1 = fmaxf(m1v, mx1);
        float al0 = exp2f(m0v - mn0), al1 = exp2f(m1v - mn1);
        m0v = mn0; m1v = mn1;

        float rs0 = 0.f, rs1 = 0.f;
#pragma unroll
        for (int f = 0; f < 8; f++) {
            if (f < 3) {
                S[f][0] = exp2_poly(S[f][0] - mn0);
                S[f][1] = exp2_poly(S[f][1] - mn0);
                S[f][2] = exp2_poly(S[f][2] - mn1);
                S[f][3] = exp2_poly(S[f][3] - mn1);
            } else {
                S[f][0] = exp2f(S[f][0] - mn0);
                S[f][1] = exp2f(S[f][1] - mn0);
                S[f][2] = exp2f(S[f][2] - mn1);
                S[f][3] = exp2f(S[f][3] - mn1);
            }
            rs0 += S[f][0] + S[f][1];
            rs1 += S[f][2] + S[f][3];
        }
        rs0 += __shfl_xor_sync(0xffffffffu, rs0, 1);
        rs0 += __shfl_xor_sync(0xffffffffu, rs0, 2);
        rs1 += __shfl_xor_sync(0xffffffffu, rs1, 1);
        rs1 += __shfl_xor_sync(0xffffffffu, rs1, 2);
        l0 = l0 * al0 + rs0;
        l1 = l1 * al1 + rs1;

#pragma unroll
        for (int f = 0; f < 8; f++) {
            O[f][0] *= al0; O[f][1] *= al0;
            O[f][2] *= al1; O[f][3] *= al1;
        }

        // ---- split P into bf16 hi/lo packs ----
        uint32_t PH[8][2], PL[8][2];
#pragma unroll
        for (int f = 0; f < 8; f++) {
            uint32_t h01 = bf16x2(S[f][0], S[f][1]);
            uint32_t h23 = bf16x2(S[f][2], S[f][3]);
            PH[f][0] = h01; PH[f][1] = h23;
            float e0 = S[f][0] - __int_as_float(h01 << 16);
            float e1 = S[f][1] - __int_as_float(h01 & 0xFFFF0000u);
            float e2 = S[f][2] - __int_as_float(h23 << 16);
            float e3 = S[f][3] - __int_as_float(h23 & 0xFFFF0000u);
            PL[f][0] = bf16x2(e0, e1);
            PL[f][1] = bf16x2(e2, e3);
        }

        // ---- O += P' V'' ----
        uint32_t vbuf = kbuf + K2SZ;
#pragma unroll
        for (int c = 0; c < 12; c++) {
            int j = (c < 4) ? c : (c < 8 ? c - 4 : c - 8);
            int vrow = (c < 4) ? 16 * c : (c < 8 ? 16 * (c - 4) : 64 + 16 * (c - 8));
            uint32_t a[4];
            if (c < 4 || c >= 8) {
                a[0] = PH[2 * j][0]; a[1] = PH[2 * j][1];
                a[2] = PH[2 * j + 1][0]; a[3] = PH[2 * j + 1][1];
            } else {
                a[0] = PL[2 * j][0]; a[1] = PL[2 * j][1];
                a[2] = PL[2 * j + 1][0]; a[3] = PL[2 * j + 1][1];
            }
#pragma unroll
            for (int p = 0; p < 4; p++) {
                uint32_t b0, b1, b2, b3;
                ldsm_x4t(b0, b1, b2, b3, vbuf + voff + vrow * VSTR + p * 32);
                mma16816(O[2 * p + 0], a, b0, b1);
                mma16816(O[2 * p + 1], a, b2, b3);
            }
        }
        __syncthreads();
    }

    // ---- epilogue: write split-bf16 into g_Xs ----
    float inv0 = 1.f / l0, inv1 = 1.f / l1;
    int b = bh >> 4, h = bh & 15;
#pragma unroll
    for (int f = 0; f < 8; f++) {
        int col = h * HD + 8 * f + cg0;
#pragma unroll
        for (int half = 0; half < 2; half++) {
            int row = b * SEQ + q0 + warp * 16 + (lane >> 2) + half * 8;
            float vx = O[f][half * 2 + 0] * (half ? inv1 : inv0);
            float vy = O[f][half * 2 + 1] * (half ? inv1 : inv0);
            uint32_t hp = bf16x2(vx, vy);
            float h0 = __int_as_float(hp << 16);
            float h1 = __int_as_float(hp & 0xFFFF0000u);
            uint32_t lp = bf16x2(vx - h0, vy - h1);
            __nv_bfloat16* dst = g_Xs + (size_t)row * KSPLIT + col;
            *(uint32_t*)(dst)        = hp;
            *(uint32_t*)(dst + 1024) = lp;
            *(uint32_t*)(dst + 2048) = hp;
        }
    }
}

// =========================================================================
extern "C" void kernel_launch(void* const* d_in, const int* in_sizes, int n_in,
                              void* d_out, int out_size)
{
    const float* x  = (const float*)d_in[0];
    const float* Wq = (const float*)d_in[2];
    const float* Wk = (const float*)d_in[3];
    const float* Wv = (const float*)d_in[4];
    const float* Wo = (const float*)d_in[5];
    float* out = (float*)d_out;

    __nv_bfloat16 *dXs, *dWs;
    cudaGetSymbolAddress((void**)&dXs, g_Xs);
    cudaGetSymbolAddress((void**)&dWs, g_Ws);

    cudaFuncSetAttribute(gemm_mma,
                         cudaFuncAttributeMaxDynamicSharedMemorySize, GEMM_SMEM);
    cudaFuncSetAttribute(flash2,
                         cudaFuncAttributeMaxDynamicSharedMemorySize, FLASH_SMEM);

    const size_t WSZ = (size_t)EMBED * KSPLIT;

    // splits for x, Wq, Wk, Wv (Wo split deferred so launch #5 = fused QKV gemm)
    split_act<<<MROWS * 1024 / 256, 256>>>(x, dXs);                    // 1
    split_wgt<<<EMBED * 1024 / 256, 256>>>(Wq, dWs + 0 * WSZ);         // 2
    split_wgt<<<EMBED * 1024 / 256, 256>>>(Wk, dWs + 1 * WSZ);         // 3
    split_wgt<<<EMBED * 1024 / 256, 256>>>(Wv, dWs + 2 * WSZ);         // 4

    // fused Q/K/V projections: grid.z selects weight slice + destination
    dim3 gQKV(EMBED / 128, MROWS / 128, 3);
    gemm_mma<<<gQKV, 256, GEMM_SMEM>>>(dXs, dWs, nullptr, 0);          // 5

    // attention (writes split A directly into g_Xs)
    dim3 gFlash(SEQ / 128, BATCH * HEADS);
    flash2<<<gFlash, 256, FLASH_SMEM>>>();                             // 6

    // O projection
    split_wgt<<<EMBED * 1024 / 256, 256>>>(Wo, dWs + 3 * WSZ);         // 7
    dim3 gO(EMBED / 128, MROWS / 128, 1);
    gemm_mma<<<gO, 256, GEMM_SMEM>>>(dXs, dWs + 3 * WSZ, out, 3);      // 8
}

// round 10
// speedup vs baseline: 1.0737x; 1.0737x over previous
#include <cuda_runtime.h>
#include <cuda_bf16.h>
#include <math.h>
#include <stdint.h>

#define EMBED  1024
#define HEADS  16
#define HD     64
#define BATCH  2
#define SEQ    2048
#define MROWS  (BATCH*SEQ)   // 4096
#define KSPLIT 3072          // 3*EMBED augmented K
#define SC2F   0.1803368801111601f   // (1/sqrt(64)) * log2(e)

// ---------------- scratch (device globals; no allocation) ----------------
__device__ __nv_bfloat16 g_Xs[MROWS*KSPLIT];       // split activations [hi|lo|hi]
__device__ __nv_bfloat16 g_Ws[4*EMBED*KSPLIT];     // split weights     [hi|hi|lo]
__device__ __nv_bfloat16 g_Qh[BATCH*HEADS*SEQ*HD]; // bf16 hi/lo, [bh][s][d]
__device__ __nv_bfloat16 g_Ql[BATCH*HEADS*SEQ*HD];
__device__ __nv_bfloat16 g_Kh[BATCH*HEADS*SEQ*HD];
__device__ __nv_bfloat16 g_Kl[BATCH*HEADS*SEQ*HD];
__device__ __nv_bfloat16 g_Vh[BATCH*HEADS*SEQ*HD];
__device__ __nv_bfloat16 g_Vl[BATCH*HEADS*SEQ*HD];

// ============================ helpers ================================
__device__ __forceinline__ uint32_t smem_u32(const void* p) {
    uint32_t a;
    asm("{ .reg .u64 t; cvta.to.shared.u64 t, %1; cvt.u32.u64 %0, t; }"
        : "=r"(a) : "l"(p));
    return a;
}
__device__ __forceinline__ void cp_async16(uint32_t dst, const void* src) {
    asm volatile("cp.async.cg.shared.global [%0], [%1], 16;"
                 :: "r"(dst), "l"(src) : "memory");
}
__device__ __forceinline__ void cp_commit() {
    asm volatile("cp.async.commit_group;" ::: "memory");
}
__device__ __forceinline__ void cp_wait0() {
    asm volatile("cp.async.wait_group 0;" ::: "memory");
}
__device__ __forceinline__ void cp_wait1() {
    asm volatile("cp.async.wait_group 1;" ::: "memory");
}
__device__ __forceinline__ void ldsm_x4(uint32_t& r0, uint32_t& r1,
                                        uint32_t& r2, uint32_t& r3, uint32_t addr) {
    asm volatile("ldmatrix.sync.aligned.m8n8.x4.shared.b16 {%0,%1,%2,%3}, [%4];"
                 : "=r"(r0), "=r"(r1), "=r"(r2), "=r"(r3) : "r"(addr));
}
__device__ __forceinline__ void ldsm_x4t(uint32_t& r0, uint32_t& r1,
                                         uint32_t& r2, uint32_t& r3, uint32_t addr) {
    asm volatile("ldmatrix.sync.aligned.m8n8.x4.trans.shared.b16 {%0,%1,%2,%3}, [%4];"
                 : "=r"(r0), "=r"(r1), "=r"(r2), "=r"(r3) : "r"(addr));
}
__device__ __forceinline__ void mma16816(float* c, const uint32_t* a,
                                         uint32_t b0, uint32_t b1) {
    asm volatile(
        "mma.sync.aligned.m16n8k16.row.col.f32.bf16.bf16.f32 "
        "{%0,%1,%2,%3}, {%4,%5,%6,%7}, {%8,%9}, {%0,%1,%2,%3};"
        : "+f"(c[0]), "+f"(c[1]), "+f"(c[2]), "+f"(c[3])
        : "r"(a[0]), "r"(a[1]), "r"(a[2]), "r"(a[3]), "r"(b0), "r"(b1));
}
// pack: lo half = a, hi half = b
__device__ __forceinline__ uint32_t bf16x2(float a, float b) {
    uint32_t r;
    asm("cvt.rn.bf16x2.f32 %0, %1, %2;" : "=r"(r) : "f"(b), "f"(a));
    return r;
}
// fma-pipe exp2 (poly-4, rel err ~4e-5), input clamped to [-80, 0]
__device__ __forceinline__ float exp2_poly(float d) {
    d = fmaxf(d, -80.f);
    float t = d + 12582912.f;
    int ib = __float_as_int(t);
    float f = d - (t - 12582912.f);
    float p = 0.009618130f;
    p = fmaf(p, f, 0.055504110f);
    p = fmaf(p, f, 0.240226507f);
    p = fmaf(p, f, 0.693147181f);
    p = fmaf(p, f, 1.0f);
    return __int_as_float(__float_as_int(p) + (ib << 23));
}

// ============================ split kernels ==============================
__global__ void split_act(const float* __restrict__ in, __nv_bfloat16* __restrict__ out) {
    int idx = blockIdx.x * 256 + threadIdx.x;
    int r = idx >> 10, c = idx & 1023;
    float v = in[idx];
    __nv_bfloat16 hi = __float2bfloat16(v);
    __nv_bfloat16 lo = __float2bfloat16(v - __bfloat162float(hi));
    size_t o = (size_t)r * KSPLIT + c;
    out[o] = hi; out[o + 1024] = lo; out[o + 2048] = hi;
}
__global__ void split_wgt(const float* __restrict__ in, __nv_bfloat16* __restrict__ out) {
    int idx = blockIdx.x * 256 + threadIdx.x;
    int r = idx >> 10, c = idx & 1023;
    float v = in[idx];
    __nv_bfloat16 hi = __float2bfloat16(v);
    __nv_bfloat16 lo = __float2bfloat16(v - __bfloat162float(hi));
    size_t o = (size_t)r * KSPLIT + c;
    out[o] = hi; out[o + 1024] = hi; out[o + 2048] = lo;
}

// ============================ HMMA GEMM ===============================
// C[4096,1024] = A'[4096,3072] * W'[1024,3072]^T  (bf16 in, fp32 accum)
// grid (8, 32, nz); mode = mode_base + blockIdx.z selects W slice + dest.
#define KTILE   64
#define NSTEP   (KSPLIT/KTILE)          // 48
#define TILE_AB (128*144)
#define BUFSZ   (2*TILE_AB)
#define GEMM_SMEM (2*BUFSZ)             // 73728

__device__ __forceinline__ void load_tile(uint32_t smb, int buf,
                                          const __nv_bfloat16* __restrict__ A,
                                          const __nv_bfloat16* __restrict__ W,
                                          int m0, int n0, int kbase, int tid) {
    uint32_t base = smb + buf * BUFSZ;
#pragma unroll
    for (int i = 0; i < 4; i++) {
        int c = tid + i * 256;
        int row = c >> 3, kc = (c & 7) * 8;
        cp_async16(base + row * 144 + kc * 2,
                   A + (size_t)(m0 + row) * KSPLIT + kbase + kc);
    }
#pragma unroll
    for (int i = 0; i < 4; i++) {
        int c = tid + i * 256;
        int row = c >> 3, kc = (c & 7) * 8;
        cp_async16(base + TILE_AB + row * 144 + kc * 2,
                   W + (size_t)(n0 + row) * KSPLIT + kbase + kc);
    }
}

__global__ __launch_bounds__(256, 2) void gemm_mma(const __nv_bfloat16* __restrict__ A,
                                                   const __nv_bfloat16* __restrict__ Wbase,
                                                   float* __restrict__ Cext, int mode_base)
{
    extern __shared__ char sm[];
    uint32_t smb = smem_u32(sm);
    int tid = threadIdx.x;
    int warp = tid >> 5, lane = tid & 31;
    int wm = warp & 1, wn = warp >> 1;
    int m0 = blockIdx.y * 128;
    int n0 = blockIdx.x * 128;
    int mode = mode_base + blockIdx.z;
    const __nv_bfloat16* W = Wbase + (size_t)blockIdx.z * EMBED * KSPLIT;

    float acc[4][4][4];
#pragma unroll
    for (int i = 0; i < 4; i++)
#pragma unroll
        for (int j = 0; j < 4; j++)
#pragma unroll
            for (int q = 0; q < 4; q++) acc[i][j][q] = 0.f;

    load_tile(smb, 0, A, W, m0, n0, 0, tid);
    cp_commit();
    cp_wait0();
    __syncthreads();

    uint32_t aoff = (uint32_t)((wm * 64 + (lane & 15)) * 144 + (lane >> 4) * 16);
    uint32_t boff = (uint32_t)(TILE_AB + (wn * 32 + (lane & 15)) * 144 + (lane >> 4) * 16);

    for (int kt = 0; kt < NSTEP; kt++) {
        int b = kt & 1;
        if (kt + 1 < NSTEP) {
            load_tile(smb, b ^ 1, A, W, m0, n0, (kt + 1) * KTILE, tid);
            cp_commit();
        }
        uint32_t abase = smb + b * BUFSZ + aoff;
        uint32_t bbase = smb + b * BUFSZ + boff;
#pragma unroll
        for (int kk = 0; kk < 4; kk++) {
            uint32_t af[4][4];
#pragma unroll
            for (int mf = 0; mf < 4; mf++)
                ldsm_x4(af[mf][0], af[mf][1], af[mf][2], af[mf][3],
                        abase + mf * 16 * 144 + kk * 32);
#pragma unroll
            for (int nb = 0; nb < 2; nb++) {
                uint32_t b0, b1, b2, b3;
                ldsm_x4(b0, b1, b2, b3, bbase + nb * 16 * 144 + kk * 32);
#pragma unroll
                for (int mf = 0; mf < 4; mf++) {
                    mma16816(acc[mf][nb * 2 + 0], af[mf], b0, b2);
                    mma16816(acc[mf][nb * 2 + 1], af[mf], b1, b3);
                }
            }
        }
        if (kt + 1 < NSTEP) cp_wait0();
        __syncthreads();
    }

    int lr = lane >> 2, lc = (lane & 3) * 2;
#pragma unroll
    for (int mf = 0; mf < 4; mf++) {
#pragma unroll
        for (int nf = 0; nf < 4; nf++) {
            int col = n0 + wn * 32 + nf * 8 + lc;
#pragma unroll
            for (int half = 0; half < 2; half++) {
                int row = m0 + wm * 64 + mf * 16 + lr + half * 8;
                float vx = acc[mf][nf][half * 2 + 0];
                float vy = acc[mf][nf][half * 2 + 1];
                if (mode == 3) {
                    *(float2*)(Cext + (size_t)row * EMBED + col) = make_float2(vx, vy);
                } else {
                    if (mode == 0) { vx *= SC2F; vy *= SC2F; }
                    uint32_t hp = bf16x2(vx, vy);
                    float h0 = __int_as_float(hp << 16);
                    float h1 = __int_as_float(hp & 0xFFFF0000u);
                    uint32_t lp = bf16x2(vx - h0, vy - h1);
                    int bb = row >> 11, s = row & 2047;
                    int h = col >> 6, d = col & 63;
                    size_t idx = (((size_t)(bb * HEADS + h) * SEQ + s) * HD + d);
                    __nv_bfloat16 *dh, *dl;
                    if (mode == 0)      { dh = g_Qh; dl = g_Ql; }
                    else if (mode == 1) { dh = g_Kh; dl = g_Kl; }
                    else                { dh = g_Vh; dl = g_Vl; }
                    *(uint32_t*)(dh + idx) = hp;
                    *(uint32_t*)(dl + idx) = lp;
                }
            }
        }
    }
}

// =========================================================================
// Flash attention: HMMA split-bf16, log2-domain softmax, hybrid exp.
// 1 CTA/SM (R7's (256,2) hint caused reg clamp + spills -> reverted).
// =========================================================================
#define QSTR  272               // Q2/K2 row stride bytes (136 bf16)
#define VSTR  144               // V2 row stride bytes (72 bf16)
#define Q2SZ  (128*QSTR)        // 34816
#define K2SZ  (64*QSTR)         // 17408
#define V2SZ  (128*VSTR)        // 18432
#define KVSZ  (K2SZ+V2SZ)
#define FLASH_SMEM (Q2SZ + 2*KVSZ)   // 106496

__device__ __forceinline__ void flash_load_kv(uint32_t smb, int buf, int k0,
                                              const __nv_bfloat16* Kh, const __nv_bfloat16* Kl,
                                              const __nv_bfloat16* Vh, const __nv_bfloat16* Vl,
                                              int tid) {
    uint32_t kb = smb + Q2SZ + buf * KVSZ;
    uint32_t vb = kb + K2SZ;
#pragma unroll
    for (int i = 0; i < 4; i++) {
        int id = tid + i * 256;
        int row = id >> 4, half = (id >> 3) & 1, c8 = id & 7;
        cp_async16(kb + row * QSTR + half * 128 + c8 * 16,
                   (half ? Kl : Kh) + (size_t)(k0 + row) * HD + c8 * 8);
    }
#pragma unroll
    for (int i = 0; i < 4; i++) {
        int id = tid + i * 256;
        int row = id >> 3, c8 = id & 7;
        cp_async16(vb + row * VSTR + c8 * 16,
                   (row < 64 ? Vh : Vl) + (size_t)(k0 + (row & 63)) * HD + c8 * 8);
    }
}

__global__ __launch_bounds__(256) void flash2()
{
    extern __shared__ char sm[];
    uint32_t smb = smem_u32(sm);
    int tid = threadIdx.x;
    int warp = tid >> 5, lane = tid & 31;
    int bh = blockIdx.y;
    int qt = (int)gridDim.x - 1 - blockIdx.x;   // heavy tiles first
    int q0 = qt * 128;

    size_t base = (size_t)bh * SEQ * HD;
    const __nv_bfloat16 *Qh = g_Qh + base, *Ql = g_Ql + base;
    const __nv_bfloat16 *Kh = g_Kh + base, *Kl = g_Kl + base;
    const __nv_bfloat16 *Vh = g_Vh + base, *Vl = g_Vl + base;

#pragma unroll
    for (int i = 0; i < 8; i++) {
        int id = tid + i * 256;
        int row = id >> 4, half = (id >> 3) & 1, c8 = id & 7;
        cp_async16(smb + row * QSTR + half * 128 + c8 * 16,
                   (half ? Ql : Qh) + (size_t)(q0 + row) * HD + c8 * 8);
    }
    flash_load_kv(smb, 0, 0, Kh, Kl, Vh, Vl, tid);
    cp_commit();

    float O[8][4];
#pragma unroll
    for (int f = 0; f < 8; f++)
#pragma unroll
        for (int q = 0; q < 4; q++) O[f][q] = 0.f;
    float m0v = -1e30f, m1v = -1e30f, l0 = 0.f, l1 = 0.f;

    uint32_t aoff = (uint32_t)((warp * 16 + (lane & 15)) * QSTR + (lane >> 4) * 16);
    uint32_t koff = (uint32_t)((lane & 15) * QSTR + (lane >> 4) * 16);
    uint32_t voff = (uint32_t)((lane & 15) * VSTR + (lane >> 4) * 16);

    int nkt = 2 * (qt + 1);
    int rg0 = q0 + warp * 16 + (lane >> 2);
    int cg0 = 2 * (lane & 3);

    for (int kt = 0; kt < nkt; kt++) {
        int buf = kt & 1;
        int k0 = kt * 64;
        if (kt + 1 < nkt) {
            flash_load_kv(smb, buf ^ 1, (kt + 1) * 64, Kh, Kl, Vh, Vl, tid);
            cp_commit();
            cp_wait1();
        } else {
            cp_wait0();
        }
        __syncthreads();

        // ---- S = Q' K'^T ----
        float S[8][4];
#pragma unroll
        for (int f = 0; f < 8; f++)
#pragma unroll
            for (int q = 0; q < 4; q++) S[f][q] = 0.f;
        uint32_t kbuf = smb + Q2SZ + buf * KVSZ;
#pragma unroll
        for (int c = 0; c < 12; c++) {
            int ac = (c < 8) ? c : c - 8;
            int bc = (c < 8) ? (c & 3) : 4 + (c & 3);
            uint32_t a[4];
            ldsm_x4(a[0], a[1], a[2], a[3], smb + aoff + ac * 32);
#pragma unroll
            for (int g = 0; g < 4; g++) {
                uint32_t b0, b1, b2, b3;
                ldsm_x4(b0, b1, b2, b3, kbuf + koff + g * 16 * QSTR + bc * 32);
                mma16816(S[2 * g + 0], a, b0, b2);
                mma16816(S[2 * g + 1], a, b1, b3);
            }
        }

        // ---- causal mask ----
        if (kt >= nkt - 2) {
#pragma unroll
            for (int f = 0; f < 8; f++) {
                int key = k0 + 8 * f + cg0;
#pragma unroll
                for (int q = 0; q < 4; q++) {
                    int kcol = key + (q & 1);
                    int row = rg0 + (q >> 1) * 8;
                    if (kcol > row) S[f][q] = -1e30f;
                }
            }
        }

        // ---- online softmax (log2 domain) ----
        float mx0 = -1e30f, mx1 = -1e30f;
#pragma unroll
        for (int f = 0; f < 8; f++) {
            mx0 = fmaxf(mx0, fmaxf(S[f][0], S[f][1]));
            mx1 = fmaxf(mx1, fmaxf(S[f][2], S[f][3]));
        }
        mx0 = fmaxf(mx0, __shfl_xor_sync(0xffffffffu, mx0, 1));
        mx0 = fmaxf(mx0, __shfl_xor_sync(0xffffffffu, mx0, 2));
        mx1 = fmaxf(mx1, __shfl_xor_sync(0xffffffffu, mx1, 1));
        mx1 = fmaxf(mx1, __shfl_xor_sync(0xffffffffu, mx1, 2));
        float mn0 = fmaxf(m0v, mx0), mn1 = fmaxf(m1v, mx1);
        float al0 = exp2f(m0v - mn0), al1 = exp2f(m1v - mn1);
        m0v = mn0; m1v = mn1;

        float rs0 = 0.f, rs1 = 0.f;
#pragma unroll
        for (int f = 0; f < 8; f++) {
            if (f < 3) {
                S[f][0] = exp2_poly(S[f][0] - mn0);
                S[f][1] = exp2_poly(S[f][1] - mn0);
                S[f][2] = exp2_poly(S[f][2] - mn1);
                S[f][3] = exp2_poly(S[f][3] - mn1);
            } else {
                S[f][0] = exp2f(S[f][0] - mn0);
                S[f][1] = exp2f(S[f][1] - mn0);
                S[f][2] = exp2f(S[f][2] - mn1);
                S[f][3] = exp2f(S[f][3] - mn1);
            }
            rs0 += S[f][0] + S[f][1];
            rs1 += S[f][2] + S[f][3];
        }
        rs0 += __shfl_xor_sync(0xffffffffu, rs0, 1);
        rs0 += __shfl_xor_sync(0xffffffffu, rs0, 2);
        rs1 += __shfl_xor_sync(0xffffffffu, rs1, 1);
        rs1 += __shfl_xor_sync(0xffffffffu, rs1, 2);
        l0 = l0 * al0 + rs0;
        l1 = l1 * al1 + rs1;

#pragma unroll
        for (int f = 0; f < 8; f++) {
            O[f][0] *= al0; O[f][1] *= al0;
            O[f][2] *= al1; O[f][3] *= al1;
        }

        // ---- split P into bf16 hi/lo packs ----
        uint32_t PH[8][2], PL[8][2];
#pragma unroll
        for (int f = 0; f < 8; f++) {
            uint32_t h01 = bf16x2(S[f][0], S[f][1]);
            uint32_t h23 = bf16x2(S[f][2], S[f][3]);
            PH[f][0] = h01; PH[f][1] = h23;
            float e0 = S[f][0] - __int_as_float(h01 << 16);
            float e1 = S[f][1] - __int_as_float(h01 & 0xFFFF0000u);
            float e2 = S[f][2] - __int_as_float(h23 << 16);
            float e3 = S[f][3] - __int_as_float(h23 & 0xFFFF0000u);
            PL[f][0] = bf16x2(e0, e1);
            PL[f][1] = bf16x2(e2, e3);
        }

        // ---- O += P' V'' ----
        uint32_t vbuf = kbuf + K2SZ;
#pragma unroll
        for (int c = 0; c < 12; c++) {
            int j = (c < 4) ? c : (c < 8 ? c - 4 : c - 8);
            int vrow = (c < 4) ? 16 * c : (c < 8 ? 16 * (c - 4) : 64 + 16 * (c - 8));
            uint32_t a[4];
            if (c < 4 || c >= 8) {
                a[0] = PH[2 * j][0]; a[1] = PH[2 * j][1];
                a[2] = PH[2 * j + 1][0]; a[3] = PH[2 * j + 1][1];
            } else {
                a[0] = PL[2 * j][0]; a[1] = PL[2 * j][1];
                a[2] = PL[2 * j + 1][0]; a[3] = PL[2 * j + 1][1];
            }
#pragma unroll
            for (int p = 0; p < 4; p++) {
                uint32_t b0, b1, b2, b3;
                ldsm_x4t(b0, b1, b2, b3, vbuf + voff + vrow * VSTR + p * 32);
                mma16816(O[2 * p + 0], a, b0, b1);
                mma16816(O[2 * p + 1], a, b2, b3);
            }
        }
        __syncthreads();
    }

    // ---- epilogue: write split-bf16 into g_Xs ----
    float inv0 = 1.f / l0, inv1 = 1.f / l1;
    int b = bh >> 4, h = bh & 15;
#pragma unroll
    for (int f = 0; f < 8; f++) {
        int col = h * HD + 8 * f + cg0;
#pragma unroll
        for (int half = 0; half < 2; half++) {
            int row = b * SEQ + q0 + warp * 16 + (lane >> 2) + half * 8;
            float vx = O[f][half * 2 + 0] * (half ? inv1 : inv0);
            float vy = O[f][half * 2 + 1] * (half ? inv1 : inv0);
            uint32_t hp = bf16x2(vx, vy);
            float h0 = __int_as_float(hp << 16);
            float h1 = __int_as_float(hp & 0xFFFF0000u);
            uint32_t lp = bf16x2(vx - h0, vy - h1);
            __nv_bfloat16* dst = g_Xs + (size_t)row * KSPLIT + col;
            *(uint32_t*)(dst)        = hp;
            *(uint32_t*)(dst + 1024) = lp;
            *(uint32_t*)(dst + 2048) = hp;
        }
    }
}

// =========================================================================
extern "C" void kernel_launch(void* const* d_in, const int* in_sizes, int n_in,
                              void* d_out, int out_size)
{
    const float* x  = (const float*)d_in[0];
    const float* Wq = (const float*)d_in[2];
    const float* Wk = (const float*)d_in[3];
    const float* Wv = (const float*)d_in[4];
    const float* Wo = (const float*)d_in[5];
    float* out = (float*)d_out;

    __nv_bfloat16 *dXs, *dWs;
    cudaGetSymbolAddress((void**)&dXs, g_Xs);
    cudaGetSymbolAddress((void**)&dWs, g_Ws);

    cudaFuncSetAttribute(gemm_mma,
                         cudaFuncAttributeMaxDynamicSharedMemorySize, GEMM_SMEM);
    cudaFuncSetAttribute(flash2,
                         cudaFuncAttributeMaxDynamicSharedMemorySize, FLASH_SMEM);

    const size_t WSZ = (size_t)EMBED * KSPLIT;

    // splits for x, Wq, Wk, Wv (Wo split deferred so launch #5 = fused QKV gemm)
    split_act<<<MROWS * 1024 / 256, 256>>>(x, dXs);                    // 1
    split_wgt<<<EMBED * 1024 / 256, 256>>>(Wq, dWs + 0 * WSZ);         // 2
    split_wgt<<<EMBED * 1024 / 256, 256>>>(Wk, dWs + 1 * WSZ);         // 3
    split_wgt<<<EMBED * 1024 / 256, 256>>>(Wv, dWs + 2 * WSZ);         // 4

    // fused Q/K/V projections: grid.z selects weight slice + destination
    dim3 gQKV(EMBED / 128, MROWS / 128, 3);
    gemm_mma<<<gQKV, 256, GEMM_SMEM>>>(dXs, dWs, nullptr, 0);          // 5

    // attention (writes split A directly into g_Xs)
    dim3 gFlash(SEQ / 128, BATCH * HEADS);
    flash2<<<gFlash, 256, FLASH_SMEM>>>();                             // 6

    // O projection
    split_wgt<<<EMBED * 1024 / 256, 256>>>(Wo, dWs + 3 * WSZ);         // 7
    dim3 gO(EMBED / 128, MROWS / 128, 1);
    gemm_mma<<<gO, 256, GEMM_SMEM>>>(dXs, dWs + 3 * WSZ, out, 3);      // 8
}

// round 13
// speedup vs baseline: 1.0961x; 1.0209x over previous
#include <cuda_runtime.h>
#include <cuda_bf16.h>
#include <math.h>
#include <stdint.h>

#define EMBED  1024
#define HEADS  16
#define HD     64
#define BATCH  2
#define SEQ    2048
#define MROWS  (BATCH*SEQ)   // 4096
#define SC2F   0.1803368801111601f   // (1/sqrt(64)) * log2(e)

// ---------------- scratch (device globals; no allocation) ----------------
__device__ __nv_bfloat16 g_Xh[MROWS*EMBED];        // activation hi / lo
__device__ __nv_bfloat16 g_Xl[MROWS*EMBED];
__device__ __nv_bfloat16 g_Wh[4*EMBED*EMBED];      // weight hi / lo (4 mats)
__device__ __nv_bfloat16 g_Wl[4*EMBED*EMBED];
__device__ __nv_bfloat16 g_Qh[BATCH*HEADS*SEQ*HD]; // bf16 hi/lo, [bh][s][d]
__device__ __nv_bfloat16 g_Ql[BATCH*HEADS*SEQ*HD];
__device__ __nv_bfloat16 g_Kh[BATCH*HEADS*SEQ*HD];
__device__ __nv_bfloat16 g_Kl[BATCH*HEADS*SEQ*HD];
__device__ __nv_bfloat16 g_Vh[BATCH*HEADS*SEQ*HD];
__device__ __nv_bfloat16 g_Vl[BATCH*HEADS*SEQ*HD];

// ============================ helpers ================================
__device__ __forceinline__ uint32_t smem_u32(const void* p) {
    uint32_t a;
    asm("{ .reg .u64 t; cvta.to.shared.u64 t, %1; cvt.u32.u64 %0, t; }"
        : "=r"(a) : "l"(p));
    return a;
}
__device__ __forceinline__ void cp_async16(uint32_t dst, const void* src) {
    asm volatile("cp.async.cg.shared.global [%0], [%1], 16;"
                 :: "r"(dst), "l"(src) : "memory");
}
__device__ __forceinline__ void cp_commit() {
    asm volatile("cp.async.commit_group;" ::: "memory");
}
__device__ __forceinline__ void cp_wait0() {
    asm volatile("cp.async.wait_group 0;" ::: "memory");
}
__device__ __forceinline__ void cp_wait1() {
    asm volatile("cp.async.wait_group 1;" ::: "memory");
}
__device__ __forceinline__ void ldsm_x4(uint32_t& r0, uint32_t& r1,
                                        uint32_t& r2, uint32_t& r3, uint32_t addr) {
    asm volatile("ldmatrix.sync.aligned.m8n8.x4.shared.b16 {%0,%1,%2,%3}, [%4];"
                 : "=r"(r0), "=r"(r1), "=r"(r2), "=r"(r3) : "r"(addr));
}
__device__ __forceinline__ void ldsm_x4t(uint32_t& r0, uint32_t& r1,
                                         uint32_t& r2, uint32_t& r3, uint32_t addr) {
    asm volatile("ldmatrix.sync.aligned.m8n8.x4.trans.shared.b16 {%0,%1,%2,%3}, [%4];"
                 : "=r"(r0), "=r"(r1), "=r"(r2), "=r"(r3) : "r"(addr));
}
__device__ __forceinline__ void mma16816(float* c, const uint32_t* a,
                                         uint32_t b0, uint32_t b1) {
    asm volatile(
        "mma.sync.aligned.m16n8k16.row.col.f32.bf16.bf16.f32 "
        "{%0,%1,%2,%3}, {%4,%5,%6,%7}, {%8,%9}, {%0,%1,%2,%3};"
        : "+f"(c[0]), "+f"(c[1]), "+f"(c[2]), "+f"(c[3])
        : "r"(a[0]), "r"(a[1]), "r"(a[2]), "r"(a[3]), "r"(b0), "r"(b1));
}
// pack: lo half = a, hi half = b
__device__ __forceinline__ uint32_t bf16x2(float a, float b) {
    uint32_t r;
    asm("cvt.rn.bf16x2.f32 %0, %1, %2;" : "=r"(r) : "f"(b), "f"(a));
    return r;
}
// fma-pipe exp2 (poly-4, rel err ~4e-5), input clamped to [-80, 0]
__device__ __forceinline__ float exp2_poly(float d) {
    d = fmaxf(d, -80.f);
    float t = d + 12582912.f;
    int ib = __float_as_int(t);
    float f = d - (t - 12582912.f);
    float p = 0.009618130f;
    p = fmaf(p, f, 0.055504110f);
    p = fmaf(p, f, 0.240226507f);
    p = fmaf(p, f, 0.693147181f);
    p = fmaf(p, f, 1.0f);
    return __int_as_float(__float_as_int(p) + (ib << 23));
}

// ============================ split kernel ==============================
// in fp32 [n x 1024] -> hi bf16, lo bf16 (separate arrays, same layout)
__global__ void split2(const float* __restrict__ in,
                       __nv_bfloat16* __restrict__ oh,
                       __nv_bfloat16* __restrict__ ol) {
    int idx = blockIdx.x * 256 + threadIdx.x;
    float v = in[idx];
    __nv_bfloat16 hi = __float2bfloat16(v);
    __nv_bfloat16 lo = __float2bfloat16(v - __bfloat162float(hi));
    oh[idx] = hi; ol[idx] = lo;
}

// ============================ HMMA GEMM ===============================
// C[4096,1024] = (Ah+Al)[4096,1024] * (Wh+Wl)[1024,1024]^T, 3-term split:
//   acc += ahi*whi + alo*whi + ahi*wlo   (alo*wlo dropped, ~2^-16 rel)
// CTA tile 128x128, real-K tile 32 (hi+lo in same smem row), 2 CTAs/SM.
// grid (8, 32, nz); mode = mode_base + blockIdx.z selects W slice + dest.
#define KR     32                      // real-K per tile
#define NKT    (EMBED/KR)              // 32 tiles
#define RSTR   144                     // row stride bytes: hi 64B | lo 64B | 16 pad
#define TILE_A (128*RSTR)              // 18432 per operand
#define STAGE  (2*TILE_A)              // 36864 (A+B)
#define GEMM_SMEM (2*STAGE)            // 73728

__device__ __forceinline__ void load_tile(uint32_t smb, int buf,
                                          const __nv_bfloat16* __restrict__ Ah,
                                          const __nv_bfloat16* __restrict__ Al,
                                          const __nv_bfloat16* __restrict__ Wh,
                                          const __nv_bfloat16* __restrict__ Wl,
                                          int m0, int n0, int kbase, int tid) {
    uint32_t base = smb + buf * STAGE;
    // A: 128 rows x {hi,lo} x 4 chunks of 16B = 1024 chunks
#pragma unroll
    for (int i = 0; i < 4; i++) {
        int id = tid + i * 256;
        int row = id >> 3, half = (id >> 2) & 1, c16 = id & 3;
        cp_async16(base + row * RSTR + half * 64 + c16 * 16,
                   (half ? Al : Ah) + (size_t)(m0 + row) * EMBED + kbase + c16 * 8);
    }
    // B: same shape
#pragma unroll
    for (int i = 0; i < 4; i++) {
        int id = tid + i * 256;
        int row = id >> 3, half = (id >> 2) & 1, c16 = id & 3;
        cp_async16(base + TILE_A + row * RSTR + half * 64 + c16 * 16,
                   (half ? Wl : Wh) + (size_t)(n0 + row) * EMBED + kbase + c16 * 8);
    }
}

__global__ __launch_bounds__(256, 2) void gemm_mma(const __nv_bfloat16* __restrict__ Ah,
                                                   const __nv_bfloat16* __restrict__ Al,
                                                   const __nv_bfloat16* __restrict__ Whb,
                                                   const __nv_bfloat16* __restrict__ Wlb,
                                                   float* __restrict__ Cext, int mode_base)
{
    extern __shared__ char sm[];
    uint32_t smb = smem_u32(sm);
    int tid = threadIdx.x;
    int warp = tid >> 5, lane = tid & 31;
    int wm = warp & 1, wn = warp >> 1;
    int m0 = blockIdx.y * 128;
    int n0 = blockIdx.x * 128;
    int mode = mode_base + blockIdx.z;
    const __nv_bfloat16* Wh = Whb + (size_t)blockIdx.z * EMBED * EMBED;
    const __nv_bfloat16* Wl = Wlb + (size_t)blockIdx.z * EMBED * EMBED;

    float acc[4][4][4];
#pragma unroll
    for (int i = 0; i < 4; i++)
#pragma unroll
        for (int j = 0; j < 4; j++)
#pragma unroll
            for (int q = 0; q < 4; q++) acc[i][j][q] = 0.f;

    load_tile(smb, 0, Ah, Al, Wh, Wl, m0, n0, 0, tid);
    cp_commit();
    cp_wait0();
    __syncthreads();

    uint32_t aoff = (uint32_t)((wm * 64 + (lane & 15)) * RSTR + (lane >> 4) * 16);
    uint32_t boff = (uint32_t)(TILE_A + (wn * 32 + (lane & 15)) * RSTR + (lane >> 4) * 16);

    for (int kt = 0; kt < NKT; kt++) {
        int b = kt & 1;
        if (kt + 1 < NKT) {
            load_tile(smb, b ^ 1, Ah, Al, Wh, Wl, m0, n0, (kt + 1) * KR, tid);
            cp_commit();
        }
        uint32_t abase = smb + b * STAGE + aoff;
        uint32_t bbase = smb + b * STAGE + boff;
#pragma unroll
        for (int kk = 0; kk < 2; kk++) {           // 2 x k16 per tile
            uint32_t ah[4][4], al[4][4];
#pragma unroll
            for (int mf = 0; mf < 4; mf++) {
                ldsm_x4(ah[mf][0], ah[mf][1], ah[mf][2], ah[mf][3],
                        abase + mf * 16 * RSTR + kk * 32);
                ldsm_x4(al[mf][0], al[mf][1], al[mf][2], al[mf][3],
                        abase + mf * 16 * RSTR + 64 + kk * 32);
            }
#pragma unroll
            for (int nb = 0; nb < 2; nb++) {
                uint32_t bh0, bh1, bh2, bh3, bl0, bl1, bl2, bl3;
                ldsm_x4(bh0, bh1, bh2, bh3, bbase + nb * 16 * RSTR + kk * 32);
                ldsm_x4(bl0, bl1, bl2, bl3, bbase + nb * 16 * RSTR + 64 + kk * 32);
#pragma unroll
                for (int mf = 0; mf < 4; mf++) {
                    mma16816(acc[mf][nb * 2 + 0], ah[mf], bh0, bh2);
                    mma16816(acc[mf][nb * 2 + 0], al[mf], bh0, bh2);
                    mma16816(acc[mf][nb * 2 + 0], ah[mf], bl0, bl2);
                    mma16816(acc[mf][nb * 2 + 1], ah[mf], bh1, bh3);
                    mma16816(acc[mf][nb * 2 + 1], al[mf], bh1, bh3);
                    mma16816(acc[mf][nb * 2 + 1], ah[mf], bl1, bl3);
                }
            }
        }
        if (kt + 1 < NKT) cp_wait0();
        __syncthreads();
    }

    int lr = lane >> 2, lc = (lane & 3) * 2;
#pragma unroll
    for (int mf = 0; mf < 4; mf++) {
#pragma unroll
        for (int nf = 0; nf < 4; nf++) {
            int col = n0 + wn * 32 + nf * 8 + lc;
#pragma unroll
            for (int half = 0; half < 2; half++) {
                int row = m0 + wm * 64 + mf * 16 + lr + half * 8;
                float vx = acc[mf][nf][half * 2 + 0];
                float vy = acc[mf][nf][half * 2 + 1];
                if (mode == 3) {
                    *(float2*)(Cext + (size_t)row * EMBED + col) = make_float2(vx, vy);
                } else {
                    if (mode == 0) { vx *= SC2F; vy *= SC2F; }
                    uint32_t hp = bf16x2(vx, vy);
                    float h0 = __int_as_float(hp << 16);
                    float h1 = __int_as_float(hp & 0xFFFF0000u);
                    uint32_t lp = bf16x2(vx - h0, vy - h1);
                    int bb = row >> 11, s = row & 2047;
                    int h = col >> 6, d = col & 63;
                    size_t idx = (((size_t)(bb * HEADS + h) * SEQ + s) * HD + d);
                    __nv_bfloat16 *dh, *dl;
                    if (mode == 0)      { dh = g_Qh; dl = g_Ql; }
                    else if (mode == 1) { dh = g_Kh; dl = g_Kl; }
                    else                { dh = g_Vh; dl = g_Vl; }
                    *(uint32_t*)(dh + idx) = hp;
                    *(uint32_t*)(dl + idx) = lp;
                }
            }
        }
    }
}

// =========================================================================
// Flash attention: HMMA split-bf16, log2-domain softmax, hybrid exp.
// 1 CTA/SM. Epilogue writes split A into g_Xh/g_Xl for the O projection.
// =========================================================================
#define QSTR  272               // Q2/K2 row stride bytes (136 bf16)
#define VSTR  144               // V2 row stride bytes (72 bf16)
#define Q2SZ  (128*QSTR)        // 34816
#define K2SZ  (64*QSTR)         // 17408
#define V2SZ  (128*VSTR)        // 18432
#define KVSZ  (K2SZ+V2SZ)
#define FLASH_SMEM (Q2SZ + 2*KVSZ)   // 106496

__device__ __forceinline__ void flash_load_kv(uint32_t smb, int buf, int k0,
                                              const __nv_bfloat16* Kh, const __nv_bfloat16* Kl,
                                              const __nv_bfloat16* Vh, const __nv_bfloat16* Vl,
                                              int tid) {
    uint32_t kb = smb + Q2SZ + buf * KVSZ;
    uint32_t vb = kb + K2SZ;
#pragma unroll
    for (int i = 0; i < 4; i++) {
        int id = tid + i * 256;
        int row = id >> 4, half = (id >> 3) & 1, c8 = id & 7;
        cp_async16(kb + row * QSTR + half * 128 + c8 * 16,
                   (half ? Kl : Kh) + (size_t)(k0 + row) * HD + c8 * 8);
    }
#pragma unroll
    for (int i = 0; i < 4; i++) {
        int id = tid + i * 256;
        int row = id >> 3, c8 = id & 7;
        cp_async16(vb + row * VSTR + c8 * 16,
                   (row < 64 ? Vh : Vl) + (size_t)(k0 + (row & 63)) * HD + c8 * 8);
    }
}

__global__ __launch_bounds__(256) void flash2()
{
    extern __shared__ char sm[];
    uint32_t smb = smem_u32(sm);
    int tid = threadIdx.x;
    int warp = tid >> 5, lane = tid & 31;
    int bh = blockIdx.y;
    int qt = (int)gridDim.x - 1 - blockIdx.x;   // heavy tiles first
    int q0 = qt * 128;

    size_t base = (size_t)bh * SEQ * HD;
    const __nv_bfloat16 *Qh = g_Qh + base, *Ql = g_Ql + base;
    const __nv_bfloat16 *Kh = g_Kh + base, *Kl = g_Kl + base;
    const __nv_bfloat16 *Vh = g_Vh + base, *Vl = g_Vl + base;

#pragma unroll
    for (int i = 0; i < 8; i++) {
        int id = tid + i * 256;
        int row = id >> 4, half = (id >> 3) & 1, c8 = id & 7;
        cp_async16(smb + row * QSTR + half * 128 + c8 * 16,
                   (half ? Ql : Qh) + (size_t)(q0 + row) * HD + c8 * 8);
    }
    flash_load_kv(smb, 0, 0, Kh, Kl, Vh, Vl, tid);
    cp_commit();

    float O[8][4];
#pragma unroll
    for (int f = 0; f < 8; f++)
#pragma unroll
        for (int q = 0; q < 4; q++) O[f][q] = 0.f;
    float m0v = -1e30f, m1v = -1e30f, l0 = 0.f, l1 = 0.f;

    uint32_t aoff = (uint32_t)((warp * 16 + (lane & 15)) * QSTR + (lane >> 4) * 16);
    uint32_t koff = (uint32_t)((lane & 15) * QSTR + (lane >> 4) * 16);
    uint32_t voff = (uint32_t)((lane & 15) * VSTR + (lane >> 4) * 16);

    int nkt = 2 * (qt + 1);
    int rg0 = q0 + warp * 16 + (lane >> 2);
    int cg0 = 2 * (lane & 3);

    for (int kt = 0; kt < nkt; kt++) {
        int buf = kt & 1;
        int k0 = kt * 64;
        if (kt + 1 < nkt) {
            flash_load_kv(smb, buf ^ 1, (kt + 1) * 64, Kh, Kl, Vh, Vl, tid);
            cp_commit();
            cp_wait1();
        } else {
            cp_wait0();
        }
        __syncthreads();

        // ---- S = Q' K'^T ----
        float S[8][4];
#pragma unroll
        for (int f = 0; f < 8; f++)
#pragma unroll
            for (int q = 0; q < 4; q++) S[f][q] = 0.f;
        uint32_t kbuf = smb + Q2SZ + buf * KVSZ;
#pragma unroll
        for (int c = 0; c < 12; c++) {
            int ac = (c < 8) ? c : c - 8;
            int bc = (c < 8) ? (c & 3) : 4 + (c & 3);
            uint32_t a[4];
            ldsm_x4(a[0], a[1], a[2], a[3], smb + aoff + ac * 32);
#pragma unroll
            for (int g = 0; g < 4; g++) {
                uint32_t b0, b1, b2, b3;
                ldsm_x4(b0, b1, b2, b3, kbuf + koff + g * 16 * QSTR + bc * 32);
                mma16816(S[2 * g + 0], a, b0, b2);
                mma16816(S[2 * g + 1], a, b1, b3);
            }
        }

        // ---- causal mask ----
        if (kt >= nkt - 2) {
#pragma unroll
            for (int f = 0; f < 8; f++) {
                int key = k0 + 8 * f + cg0;
#pragma unroll
                for (int q = 0; q < 4; q++) {
                    int kcol = key + (q & 1);
                    int row = rg0 + (q >> 1) * 8;
                    if (kcol > row) S[f][q] = -1e30f;
                }
            }
        }

        // ---- online softmax (log2 domain) ----
        float mx0 = -1e30f, mx1 = -1e30f;
#pragma unroll
        for (int f = 0; f < 8; f++) {
            mx0 = fmaxf(mx0, fmaxf(S[f][0], S[f][1]));
            mx1 = fmaxf(mx1, fmaxf(S[f][2], S[f][3]));
        }
        mx0 = fmaxf(mx0, __shfl_xor_sync(0xffffffffu, mx0, 1));
        mx0 = fmaxf(mx0, __shfl_xor_sync(0xffffffffu, mx0, 2));
        mx1 = fmaxf(mx1, __shfl_xor_sync(0xffffffffu, mx1, 1));
        mx1 = fmaxf(mx1, __shfl_xor_sync(0xffffffffu, mx1, 2));
        float mn0 = fmaxf(m0v, mx0), mn1 = fmaxf(m1v, mx1);
        float al0 = exp2f(m0v - mn0), al1 = exp2f(m1v - mn1);
        m0v = mn0; m1v = mn1;

        float rs0 = 0.f, rs1 = 0.f;
#pragma unroll
        for (int f = 0; f < 8; f++) {
            if (f < 3) {
                S[f][0] = exp2_poly(S[f][0] - mn0);
                S[f][1] = exp2_poly(S[f][1] - mn0);
                S[f][2] = exp2_poly(S[f][2] - mn1);
                S[f][3] = exp2_poly(S[f][3] - mn1);
            } else {
                S[f][0] = exp2f(S[f][0] - mn0);
                S[f][1] = exp2f(S[f][1] - mn0);
                S[f][2] = exp2f(S[f][2] - mn1);
                S[f][3] = exp2f(S[f][3] - mn1);
            }
            rs0 += S[f][0] + S[f][1];
            rs1 += S[f][2] + S[f][3];
        }
        rs0 += __shfl_xor_sync(0xffffffffu, rs0, 1);
        rs0 += __shfl_xor_sync(0xffffffffu, rs0, 2);
        rs1 += __shfl_xor_sync(0xffffffffu, rs1, 1);
        rs1 += __shfl_xor_sync(0xffffffffu, rs1, 2);
        l0 = l0 * al0 + rs0;
        l1 = l1 * al1 + rs1;

#pragma unroll
        for (int f = 0; f < 8; f++) {
            O[f][0] *= al0; O[f][1] *= al0;
            O[f][2] *= al1; O[f][3] *= al1;
        }

        // ---- split P into bf16 hi/lo packs ----
        uint32_t PH[8][2], PL[8][2];
#pragma unroll
        for (int f = 0; f < 8; f++) {
            uint32_t h01 = bf16x2(S[f][0], S[f][1]);
            uint32_t h23 = bf16x2(S[f][2], S[f][3]);
            PH[f][0] = h01; PH[f][1] = h23;
            float e0 = S[f][0] - __int_as_float(h01 << 16);
            float e1 = S[f][1] - __int_as_float(h01 & 0xFFFF0000u);
            float e2 = S[f][2] - __int_as_float(h23 << 16);
            float e3 = S[f][3] - __int_as_float(h23 & 0xFFFF0000u);
            PL[f][0] = bf16x2(e0, e1);
            PL[f][1] = bf16x2(e2, e3);
        }

        // ---- O += P' V'' ----
        uint32_t vbuf = kbuf + K2SZ;
#pragma unroll
        for (int c = 0; c < 12; c++) {
            int j = (c < 4) ? c : (c < 8 ? c - 4 : c - 8);
            int vrow = (c < 4) ? 16 * c : (c < 8 ? 16 * (c - 4) : 64 + 16 * (c - 8));
            uint32_t a[4];
            if (c < 4 || c >= 8) {
                a[0] = PH[2 * j][0]; a[1] = PH[2 * j][1];
                a[2] = PH[2 * j + 1][0]; a[3] = PH[2 * j + 1][1];
            } else {
                a[0] = PL[2 * j][0]; a[1] = PL[2 * j][1];
                a[2] = PL[2 * j + 1][0]; a[3] = PL[2 * j + 1][1];
            }
#pragma unroll
            for (int p = 0; p < 4; p++) {
                uint32_t b0, b1, b2, b3;
                ldsm_x4t(b0, b1, b2, b3, vbuf + voff + vrow * VSTR + p * 32);
                mma16816(O[2 * p + 0], a, b0, b1);
                mma16816(O[2 * p + 1], a, b2, b3);
            }
        }
        __syncthreads();
    }

    // ---- epilogue: write split-bf16 into g_Xh / g_Xl ----
    float inv0 = 1.f / l0, inv1 = 1.f / l1;
    int b = bh >> 4, h = bh & 15;
#pragma unroll
    for (int f = 0; f < 8; f++) {
        int col = h * HD + 8 * f + cg0;
#pragma unroll
        for (int half = 0; half < 2; half++) {
            int row = b * SEQ + q0 + warp * 16 + (lane >> 2) + half * 8;
            float vx = O[f][half * 2 + 0] * (half ? inv1 : inv0);
            float vy = O[f][half * 2 + 1] * (half ? inv1 : inv0);
            uint32_t hp = bf16x2(vx, vy);
            float h0 = __int_as_float(hp << 16);
            float h1 = __int_as_float(hp & 0xFFFF0000u);
            uint32_t lp = bf16x2(vx - h0, vy - h1);
            size_t o = (size_t)row * EMBED + col;
            *(uint32_t*)(g_Xh + o) = hp;
            *(uint32_t*)(g_Xl + o) = lp;
        }
    }
}

// =========================================================================
extern "C" void kernel_launch(void* const* d_in, const int* in_sizes, int n_in,
                              void* d_out, int out_size)
{
    const float* x  = (const float*)d_in[0];
    const float* Wq = (const float*)d_in[2];
    const float* Wk = (const float*)d_in[3];
    const float* Wv = (const float*)d_in[4];
    const float* Wo = (const float*)d_in[5];
    float* out = (float*)d_out;

    __nv_bfloat16 *dXh, *dXl, *dWh, *dWl;
    cudaGetSymbolAddress((void**)&dXh, g_Xh);
    cudaGetSymbolAddress((void**)&dXl, g_Xl);
    cudaGetSymbolAddress((void**)&dWh, g_Wh);
    cudaGetSymbolAddress((void**)&dWl, g_Wl);

    cudaFuncSetAttribute(gemm_mma,
                         cudaFuncAttributeMaxDynamicSharedMemorySize, GEMM_SMEM);
    cudaFuncSetAttribute(flash2,
                         cudaFuncAttributeMaxDynamicSharedMemorySize, FLASH_SMEM);

    const size_t WSZ = (size_t)EMBED * EMBED;

    // splits
    split2<<<MROWS * 1024 / 256, 256>>>(x, dXh, dXl);                  // 1
    split2<<<EMBED * 1024 / 256, 256>>>(Wq, dWh + 0 * WSZ, dWl + 0 * WSZ); // 2
    split2<<<EMBED * 1024 / 256, 256>>>(Wk, dWh + 1 * WSZ, dWl + 1 * WSZ); // 3
    split2<<<EMBED * 1024 / 256, 256>>>(Wv, dWh + 2 * WSZ, dWl + 2 * WSZ); // 4
    split2<<<EMBED * 1024 / 256, 256>>>(Wo, dWh + 3 * WSZ, dWl + 3 * WSZ); // 5

    // fused Q/K/V projections
    dim3 gQKV(EMBED / 128, MROWS / 128, 3);
    gemm_mma<<<gQKV, 256, GEMM_SMEM>>>(dXh, dXl, dWh, dWl, nullptr, 0);    // 6

    // attention (writes split A into g_Xh/g_Xl)
    dim3 gFlash(SEQ / 128, BATCH * HEADS);
    flash2<<<gFlash, 256, FLASH_SMEM>>>();                             // 7

    // O projection
    dim3 gO(EMBED / 128, MROWS / 128, 1);
    gemm_mma<<<gO, 256, GEMM_SMEM>>>(dXh, dXl, dWh + 3 * WSZ, dWl + 3 * WSZ,
                                     out, 3);                          // 8
}